// round 2
// baseline (speedup 1.0000x reference)
#include <cuda_runtime.h>
#include <cstdint>

// Problem shape (fixed by the reference): x,y are [NT, NS, NR] float32.
#define NT 4000
#define NS 16
#define NR 512
#define NCOLS (NS * NR)          // 8192 columns, contiguous innermost
#define T_CHUNK 100
#define N_TCHUNK (NT / T_CHUNK)  // 40
#define CBLK 128                 // threads per block; each thread owns 4 columns
#define NXBLK (NCOLS / 4 / CBLK) // 16

// Scratch: per-array, per-column packed (value_bits<<32 | ~t) running max.
// __device__ global (allocation-free scratch, per harness rules).
__device__ unsigned long long g_best[2][NCOLS];

__global__ void tt_init_kernel() {
    int i = blockIdx.x * blockDim.x + threadIdx.x;
    if (i < 2 * NCOLS) ((unsigned long long*)g_best)[i] = 0ULL;
}

__global__ __launch_bounds__(CBLK) void tt_argmax_kernel(const float* __restrict__ x,
                                                         const float* __restrict__ y) {
    const float* __restrict__ src = (blockIdx.z == 0) ? x : y;
    const int c4  = blockIdx.x * CBLK + threadIdx.x;   // 0..2047
    const int col = c4 * 4;                            // base column (float4 aligned)
    const int t0  = blockIdx.y * T_CHUNK;

    float        bv0 = -1.f, bv1 = -1.f, bv2 = -1.f, bv3 = -1.f;
    unsigned int bt0 = 0,    bt1 = 0,    bt2 = 0,    bt3 = 0;

    const float4* p = (const float4*)(src + (size_t)t0 * NCOLS + col);

#pragma unroll 10
    for (int t = t0; t < t0 + T_CHUNK; ++t) {
        float4 v = __ldcs(p);            // streaming: no reuse, evict-first
        p += NCOLS / 4;
        float s0 = v.x * v.x, s1 = v.y * v.y, s2 = v.z * v.z, s3 = v.w * v.w;
        // strict '>' keeps the EARLIEST t on exact ties (jnp.argmax semantics)
        if (s0 > bv0) { bv0 = s0; bt0 = (unsigned)t; }
        if (s1 > bv1) { bv1 = s1; bt1 = (unsigned)t; }
        if (s2 > bv2) { bv2 = s2; bt2 = (unsigned)t; }
        if (s3 > bv3) { bv3 = s3; bt3 = (unsigned)t; }
    }

    // Pack: (float bits, monotone since v^2 >= 0) << 32 | ~t.
    // atomicMax => largest value wins; on equal value bits, largest ~t == smallest t wins.
    unsigned long long* dst = g_best[blockIdx.z];
    unsigned long long p0 = ((unsigned long long)__float_as_uint(bv0) << 32) | (0xFFFFFFFFu - bt0);
    unsigned long long p1 = ((unsigned long long)__float_as_uint(bv1) << 32) | (0xFFFFFFFFu - bt1);
    unsigned long long p2 = ((unsigned long long)__float_as_uint(bv2) << 32) | (0xFFFFFFFFu - bt2);
    unsigned long long p3 = ((unsigned long long)__float_as_uint(bv3) << 32) | (0xFFFFFFFFu - bt3);
    atomicMax(dst + col + 0, p0);
    atomicMax(dst + col + 1, p1);
    atomicMax(dst + col + 2, p2);
    atomicMax(dst + col + 3, p3);
}

__global__ __launch_bounds__(256) void tt_reduce_kernel(float* out) {
    __shared__ unsigned long long sacc[256];
    unsigned long long acc = 0;
    for (int i = threadIdx.x; i < NCOLS; i += 256) {
        unsigned int tx = 0xFFFFFFFFu - (unsigned int)(g_best[0][i] & 0xFFFFFFFFull);
        unsigned int ty = 0xFFFFFFFFu - (unsigned int)(g_best[1][i] & 0xFFFFFFFFull);
        long long d = (long long)tx - (long long)ty;
        acc += (unsigned long long)(d * d);   // exact integer arithmetic
    }
    sacc[threadIdx.x] = acc;
    __syncthreads();
    for (int s = 128; s > 0; s >>= 1) {
        if (threadIdx.x < s) sacc[threadIdx.x] += sacc[threadIdx.x + s];
        __syncthreads();
    }
    if (threadIdx.x == 0)
        out[0] = (float)((double)sacc[0] / (double)NCOLS);
}

extern "C" void kernel_launch(void* const* d_in, const int* in_sizes, int n_in,
                              void* d_out, int out_size) {
    const float* x = (const float*)d_in[0];
    const float* y = (const float*)d_in[1];
    float* out = (float*)d_out;

    tt_init_kernel<<<(2 * NCOLS + 255) / 256, 256>>>();
    dim3 grid(NXBLK, N_TCHUNK, 2);
    tt_argmax_kernel<<<grid, CBLK>>>(x, y);
    tt_reduce_kernel<<<1, 256>>>(out);
}